// round 1
// baseline (speedup 1.0000x reference)
#include <cuda_runtime.h>
#include <math.h>

#define B_   8192
#define L_   10
#define NT_  26
#define V_   200000
#define D_   64

// scratch: h1(512) h2(256) T(27*64=1728) R(416) z1(512) z2(256) per batch row
// total per row = 3680 floats
__device__ float g_scratch[(size_t)B_ * 3680];

// ---------------------------------------------------------------------------
// Bottom MLP layer 1: [B,13] x [512,13]^T + b, ReLU  -> h1 [B,512]
// One block handles 16 batch rows, W resident in smem.
// ---------------------------------------------------------------------------
__global__ void __launch_bounds__(256) botl1_kernel(
    const float* __restrict__ x, const float* __restrict__ W,
    const float* __restrict__ bias, float* __restrict__ h1)
{
    __shared__ float Ws[512 * 13];
    __shared__ float bs[512];
    __shared__ float xs[16 * 13];
    int r0 = blockIdx.x * 16;
    for (int i = threadIdx.x; i < 512 * 13; i += 256) Ws[i] = W[i];
    for (int i = threadIdx.x; i < 512; i += 256) bs[i] = bias[i];
    for (int i = threadIdx.x; i < 16 * 13; i += 256) xs[i] = x[r0 * 13 + i];
    __syncthreads();
    #pragma unroll
    for (int cp = 0; cp < 2; cp++) {
        int c = threadIdx.x + cp * 256;
        float wreg[13];
        #pragma unroll
        for (int k = 0; k < 13; k++) wreg[k] = Ws[c * 13 + k];
        float bb = bs[c];
        #pragma unroll
        for (int r = 0; r < 16; r++) {
            float acc = bb;
            #pragma unroll
            for (int k = 0; k < 13; k++) acc = fmaf(wreg[k], xs[r * 13 + k], acc);
            h1[(size_t)(r0 + r) * 512 + c] = fmaxf(acc, 0.f);
        }
    }
}

// ---------------------------------------------------------------------------
// Generic fp32 GEMM: out[M,N] = act(X[M,K(lda)] @ W[N,K]^T + bias)
// BM=128 BN=64 BK=16, 256 threads, 8x4 register tile. ACT: 0=none 1=relu
// ---------------------------------------------------------------------------
#define BM 128
#define BN 64
#define BK 16

template<int ACT>
__global__ void __launch_bounds__(256) gemm_kernel(
    const float* __restrict__ X, int lda,
    const float* __restrict__ W,
    const float* __restrict__ bias,
    float* __restrict__ out, int ldc,
    int M, int N, int K)
{
    __shared__ float As[BK][BM + 4];
    __shared__ float Bs[BK][BN + 4];
    int tid = threadIdx.x;
    int m0 = blockIdx.x * BM;
    int n0 = blockIdx.y * BN;

    int tx = tid % 16;           // col group (4 cols)
    int ty = tid / 16;           // row group (8 rows)
    int row = ty * 8;
    int col = tx * 4;

    float acc[8][4];
    #pragma unroll
    for (int i = 0; i < 8; i++)
        #pragma unroll
        for (int j = 0; j < 4; j++) acc[i][j] = 0.f;

    int lk = tid % 16;
    int lm = tid / 16;

    for (int k0 = 0; k0 < K; k0 += BK) {
        bool kin = (k0 + lk) < K;
        #pragma unroll
        for (int p = 0; p < 8; p++) {
            int m = lm + p * 16;
            As[lk][m] = kin ? X[(size_t)(m0 + m) * lda + k0 + lk] : 0.f;
        }
        #pragma unroll
        for (int p = 0; p < 4; p++) {
            int n = lm + p * 16;
            Bs[lk][n] = kin ? W[(size_t)(n0 + n) * K + k0 + lk] : 0.f;
        }
        __syncthreads();
        #pragma unroll
        for (int k = 0; k < BK; k++) {
            float a[8], b[4];
            #pragma unroll
            for (int i = 0; i < 8; i++) a[i] = As[k][row + i];
            #pragma unroll
            for (int j = 0; j < 4; j++) b[j] = Bs[k][col + j];
            #pragma unroll
            for (int i = 0; i < 8; i++)
                #pragma unroll
                for (int j = 0; j < 4; j++)
                    acc[i][j] = fmaf(a[i], b[j], acc[i][j]);
        }
        __syncthreads();
    }
    #pragma unroll
    for (int i = 0; i < 8; i++) {
        int m = m0 + row + i;
        #pragma unroll
        for (int j = 0; j < 4; j++) {
            int n = n0 + col + j;
            float v = acc[i][j] + bias[n];
            if (ACT == 1) v = fmaxf(v, 0.f);
            out[(size_t)m * ldc + n] = v;
        }
    }
}

// ---------------------------------------------------------------------------
// Embedding bag sum pooling. 16 threads per bag (float4 per thread over D=64),
// writes directly into T[b][1+t][:] (T row-major [B][27][64]).
// ---------------------------------------------------------------------------
__global__ void __launch_bounds__(256) emb_pool_kernel(
    const int* __restrict__ lS_i, const float* __restrict__ tables,
    float* __restrict__ T)
{
    int gid = blockIdx.x * 256 + threadIdx.x;
    int bag = gid >> 4;
    int lane = gid & 15;
    if (bag >= NT_ * B_) return;
    int t = bag / B_;
    int b = bag - t * B_;
    const int* idx = lS_i + (size_t)t * (B_ * L_) + (size_t)b * L_;
    const float* tab = tables + (size_t)t * V_ * D_;
    float4 acc = make_float4(0.f, 0.f, 0.f, 0.f);
    #pragma unroll
    for (int l = 0; l < L_; l++) {
        int r = idx[l];
        float4 v = ((const float4*)(tab + (size_t)r * D_))[lane];
        acc.x += v.x; acc.y += v.y; acc.z += v.z; acc.w += v.w;
    }
    ((float4*)(T + (size_t)b * 1728 + (size_t)(t + 1) * 64))[lane] = acc;
}

// ---------------------------------------------------------------------------
// Dot interaction: per batch row, Z = T T^T lower triangle (351 pairs),
// R[b] = [h(64), Z_lt(351)], R row stride 416.
// ---------------------------------------------------------------------------
__global__ void __launch_bounds__(128) interact_kernel(
    const float* __restrict__ T, float* __restrict__ R)
{
    __shared__ float s[27 * 64];
    int b = blockIdx.x;
    const float* Tb = T + (size_t)b * 1728;
    for (int i = threadIdx.x; i < 1728; i += 128) s[i] = Tb[i];
    __syncthreads();
    float* Rb = R + (size_t)b * 416;
    if (threadIdx.x < 64) Rb[threadIdx.x] = s[threadIdx.x];
    int off = threadIdx.x & 31;   // lane rotation -> conflict-free smem reads
    for (int p = threadIdx.x; p < 351; p += 128) {
        int i = (int)((sqrtf(8.f * (float)p + 1.f) + 1.f) * 0.5f);
        while (i * (i - 1) / 2 > p) i--;
        while ((i + 1) * i / 2 <= p) i++;
        int j = p - i * (i - 1) / 2;
        const float* a = s + i * 64;
        const float* c = s + j * 64;
        float d = 0.f;
        #pragma unroll
        for (int kk = 0; kk < 64; kk++) {
            int k = (kk + off) & 63;
            d = fmaf(a[k], c[k], d);
        }
        Rb[64 + p] = d;
    }
}

// ---------------------------------------------------------------------------
// Top MLP layer 3: [B,256] x [1,256]^T + b -> sigmoid -> out [B,1]
// One warp per batch row.
// ---------------------------------------------------------------------------
__global__ void __launch_bounds__(256) top3_kernel(
    const float* __restrict__ z2, const float* __restrict__ W,
    const float* __restrict__ bias, float* __restrict__ out)
{
    int warp = (blockIdx.x * 256 + threadIdx.x) >> 5;
    int lane = threadIdx.x & 31;
    if (warp >= B_) return;
    const float* zr = z2 + (size_t)warp * 256;
    float acc = 0.f;
    #pragma unroll
    for (int u = 0; u < 8; u++) acc = fmaf(zr[lane + 32 * u], W[lane + 32 * u], acc);
    #pragma unroll
    for (int o = 16; o > 0; o >>= 1) acc += __shfl_xor_sync(0xffffffffu, acc, o);
    if (lane == 0) out[warp] = 1.f / (1.f + expf(-(acc + bias[0])));
}

// ---------------------------------------------------------------------------
extern "C" void kernel_launch(void* const* d_in, const int* in_sizes, int n_in,
                              void* d_out, int out_size)
{
    const float* x    = (const float*)d_in[0];
    const int*   lS_i = (const int*)d_in[1];
    // d_in[2] = lS_o (offsets) unused: fixed bag length L
    const float* emb  = (const float*)d_in[3];
    const float* bW1  = (const float*)d_in[4];
    const float* bb1  = (const float*)d_in[5];
    const float* bW2  = (const float*)d_in[6];
    const float* bb2  = (const float*)d_in[7];
    const float* bW3  = (const float*)d_in[8];
    const float* bb3  = (const float*)d_in[9];
    const float* tW1  = (const float*)d_in[10];
    const float* tb1  = (const float*)d_in[11];
    const float* tW2  = (const float*)d_in[12];
    const float* tb2  = (const float*)d_in[13];
    const float* tW3  = (const float*)d_in[14];
    const float* tb3  = (const float*)d_in[15];
    float* out = (float*)d_out;

    float* base;
    cudaGetSymbolAddress((void**)&base, g_scratch);
    float* h1 = base;                       // [B,512]
    float* h2 = h1 + (size_t)B_ * 512;      // [B,256]
    float* T  = h2 + (size_t)B_ * 256;      // [B,27,64]
    float* R  = T  + (size_t)B_ * 1728;     // [B,416] (415 used)
    float* z1 = R  + (size_t)B_ * 416;      // [B,512]
    float* z2 = z1 + (size_t)B_ * 512;      // [B,256]

    // embedding pooling (independent of MLP; writes T rows 1..26)
    emb_pool_kernel<<<(NT_ * B_ * 16) / 256, 256>>>(lS_i, emb, T);

    // bottom MLP
    botl1_kernel<<<B_ / 16, 256>>>(x, bW1, bb1, h1);
    gemm_kernel<1><<<dim3(B_ / BM, 256 / BN), 256>>>(h1, 512, bW2, bb2, h2, 256,
                                                     B_, 256, 512);
    gemm_kernel<1><<<dim3(B_ / BM, 64 / BN), 256>>>(h2, 256, bW3, bb3, T, 1728,
                                                    B_, 64, 256);

    // interaction
    interact_kernel<<<B_, 128>>>(T, R);

    // top MLP
    gemm_kernel<1><<<dim3(B_ / BM, 512 / BN), 256>>>(R, 416, tW1, tb1, z1, 512,
                                                     B_, 512, 415);
    gemm_kernel<1><<<dim3(B_ / BM, 256 / BN), 256>>>(z1, 512, tW2, tb2, z2, 256,
                                                     B_, 256, 512);
    top3_kernel<<<(B_ * 32) / 256, 256>>>(z2, tW3, tb3, out);
}

// round 2
// speedup vs baseline: 1.0258x; 1.0258x over previous
#include <cuda_runtime.h>
#include <mma.h>
#include <math.h>

using namespace nvcuda;

#define B_   8192
#define L_   10
#define NT_  26
#define V_   200000

// per-row scratch: h1(512) h2(256) h3(64) T26(1664) R(416) z1(512) z2(256) = 3680
// plus padded top_W1 [512][416]
__device__ __align__(256) float g_scratch[(size_t)B_ * 3680 + 512 * 416];

// ---------------------------------------------------------------------------
// cp.async helpers
// ---------------------------------------------------------------------------
__device__ __forceinline__ void cp16(void* smem, const void* gmem) {
    unsigned s = (unsigned)__cvta_generic_to_shared(smem);
    asm volatile("cp.async.ca.shared.global [%0], [%1], 16;\n" :: "r"(s), "l"(gmem));
}
__device__ __forceinline__ void cp_commit() { asm volatile("cp.async.commit_group;\n"); }
template<int N> __device__ __forceinline__ void cp_wait() {
    asm volatile("cp.async.wait_group %0;\n" :: "n"(N));
}

// ---------------------------------------------------------------------------
// Bottom MLP layer 1: [B,13] x [512,13]^T + b, ReLU -> h1 [B,512]
// ---------------------------------------------------------------------------
__global__ void __launch_bounds__(256) botl1_kernel(
    const float* __restrict__ x, const float* __restrict__ W,
    const float* __restrict__ bias, float* __restrict__ h1)
{
    __shared__ float Ws[512 * 13];
    __shared__ float bs[512];
    __shared__ float xs[16 * 13];
    int r0 = blockIdx.x * 16;
    for (int i = threadIdx.x; i < 512 * 13; i += 256) Ws[i] = W[i];
    for (int i = threadIdx.x; i < 512; i += 256) bs[i] = bias[i];
    for (int i = threadIdx.x; i < 16 * 13; i += 256) xs[i] = x[r0 * 13 + i];
    __syncthreads();
    #pragma unroll
    for (int cp = 0; cp < 2; cp++) {
        int c = threadIdx.x + cp * 256;
        float wreg[13];
        #pragma unroll
        for (int k = 0; k < 13; k++) wreg[k] = Ws[c * 13 + k];
        float bb = bs[c];
        #pragma unroll
        for (int r = 0; r < 16; r++) {
            float acc = bb;
            #pragma unroll
            for (int k = 0; k < 13; k++) acc = fmaf(wreg[k], xs[r * 13 + k], acc);
            h1[(size_t)(r0 + r) * 512 + c] = fmaxf(acc, 0.f);
        }
    }
}

// ---------------------------------------------------------------------------
// tf32 wmma GEMM: out[M,N] = relu(X[M,lda] @ W[N,ldw]^T + bias)
// 256 threads = 8 warps in WR x WC layout. BK=16, double-buffered cp.async.
// ---------------------------------------------------------------------------
#define BK   16
#define KPAD 20

template<int BM, int BN, int WR, int WC>
__global__ void __launch_bounds__(256) gemm_tf32(
    const float* __restrict__ X, int lda,
    const float* __restrict__ W, int ldw,
    const float* __restrict__ bias,
    float* __restrict__ out, int ldc, int K)
{
    constexpr int WTM = BM / WR;
    constexpr int WTN = BN / WC;
    constexpr int FM = WTM / 16;
    constexpr int FN = WTN / 16;
    __shared__ float As[2][BM][KPAD];
    __shared__ float Bs[2][BN][KPAD];
    int tid = threadIdx.x;
    int warp = tid >> 5;
    int lane = tid & 31;
    int wm = warp / WC, wn = warp % WC;
    int m0 = blockIdx.x * BM, n0 = blockIdx.y * BN;

    wmma::fragment<wmma::accumulator, 16, 16, 8, float> acc[FM][FN];
    #pragma unroll
    for (int i = 0; i < FM; i++)
        #pragma unroll
        for (int j = 0; j < FN; j++) wmma::fill_fragment(acc[i][j], 0.f);

    auto load_tile = [&](int buf, int k0) {
        #pragma unroll
        for (int i = tid; i < BM * 4; i += 256) {
            int r = i >> 2, s = (i & 3) * 4;
            cp16(&As[buf][r][s], X + (size_t)(m0 + r) * lda + k0 + s);
        }
        #pragma unroll
        for (int i = tid; i < BN * 4; i += 256) {
            int r = i >> 2, s = (i & 3) * 4;
            cp16(&Bs[buf][r][s], W + (size_t)(n0 + r) * ldw + k0 + s);
        }
        cp_commit();
    };

    int nIter = K / BK;
    load_tile(0, 0);
    int buf = 0;
    for (int it = 0; it < nIter; it++) {
        if (it + 1 < nIter) { load_tile(buf ^ 1, (it + 1) * BK); cp_wait<1>(); }
        else cp_wait<0>();
        __syncthreads();
        #pragma unroll
        for (int ks = 0; ks < 2; ks++) {
            wmma::fragment<wmma::matrix_a, 16, 16, 8, wmma::precision::tf32, wmma::row_major> af[FM];
            wmma::fragment<wmma::matrix_b, 16, 16, 8, wmma::precision::tf32, wmma::col_major> bf[FN];
            #pragma unroll
            for (int mi = 0; mi < FM; mi++) {
                wmma::load_matrix_sync(af[mi], &As[buf][wm * WTM + mi * 16][ks * 8], KPAD);
                #pragma unroll
                for (int t = 0; t < af[mi].num_elements; t++)
                    af[mi].x[t] = wmma::__float_to_tf32(af[mi].x[t]);
            }
            #pragma unroll
            for (int nj = 0; nj < FN; nj++) {
                wmma::load_matrix_sync(bf[nj], &Bs[buf][wn * WTN + nj * 16][ks * 8], KPAD);
                #pragma unroll
                for (int t = 0; t < bf[nj].num_elements; t++)
                    bf[nj].x[t] = wmma::__float_to_tf32(bf[nj].x[t]);
            }
            #pragma unroll
            for (int mi = 0; mi < FM; mi++)
                #pragma unroll
                for (int nj = 0; nj < FN; nj++)
                    wmma::mma_sync(acc[mi][nj], af[mi], bf[nj], acc[mi][nj]);
        }
        __syncthreads();
        buf ^= 1;
    }

    // epilogue: per-warp 16x16 staging in (now free) As space, +bias, relu
    float* es = &As[0][0][0] + warp * 16 * KPAD;
    #pragma unroll
    for (int mi = 0; mi < FM; mi++) {
        #pragma unroll
        for (int nj = 0; nj < FN; nj++) {
            wmma::store_matrix_sync(es, acc[mi][nj], KPAD, wmma::mem_row_major);
            __syncwarp();
            int r = lane >> 1, c0 = (lane & 1) * 8;
            int gm = m0 + wm * WTM + mi * 16 + r;
            int gn = n0 + wn * WTN + nj * 16 + c0;
            #pragma unroll
            for (int c = 0; c < 8; c++) {
                float v = es[r * KPAD + c0 + c] + bias[gn + c];
                out[(size_t)gm * ldc + gn + c] = fmaxf(v, 0.f);
            }
            __syncwarp();
        }
    }
}

// ---------------------------------------------------------------------------
// Embedding bag sum pooling -> T26 [B][26][64] (stride 1664)
// ---------------------------------------------------------------------------
__global__ void __launch_bounds__(256) emb_pool_kernel(
    const int* __restrict__ lS_i, const float* __restrict__ tables,
    float* __restrict__ T26)
{
    int gid = blockIdx.x * 256 + threadIdx.x;
    int bag = gid >> 4;
    int lane = gid & 15;
    if (bag >= NT_ * B_) return;
    int t = bag / B_;
    int b = bag - t * B_;
    const int* idx = lS_i + (size_t)t * (B_ * L_) + (size_t)b * L_;
    const float* tab = tables + (size_t)t * V_ * 64;
    float4 acc = make_float4(0.f, 0.f, 0.f, 0.f);
    #pragma unroll
    for (int l = 0; l < L_; l++) {
        int r = idx[l];
        float4 v = ((const float4*)(tab + (size_t)r * 64))[lane];
        acc.x += v.x; acc.y += v.y; acc.z += v.z; acc.w += v.w;
    }
    ((float4*)(T26 + (size_t)b * 1664 + (size_t)t * 64))[lane] = acc;
}

// ---------------------------------------------------------------------------
// Dot interaction via wmma: per batch row, Z = T T^T (T = 27x64 padded to 32),
// R[b] = [h3(64), tril(Z) 351], stride 416, col 415 zeroed.
// 8 warps = 8 rows per block.
// ---------------------------------------------------------------------------
#define TLD 68  // 64 + 4, leading dim for sT rows (272B, mult of 16)

__global__ void __launch_bounds__(256) interact_kernel(
    const float* __restrict__ h3, const float* __restrict__ T26,
    float* __restrict__ R)
{
    extern __shared__ float sT[];          // 8 * 32 * TLD floats
    __shared__ float sZ[8][16][KPAD];
    int tid = threadIdx.x, warp = tid >> 5, lane = tid & 31;
    int b0 = blockIdx.x * 8;

    for (int idx = tid; idx < 8 * 32 * 64; idx += 256) {
        int row = idx >> 11;
        int e = idx & 2047;
        int i = e >> 6, d = e & 63;
        float v = 0.f;
        if (i == 0)       v = h3[(size_t)(b0 + row) * 64 + d];
        else if (i < 27)  v = T26[(size_t)(b0 + row) * 1664 + (i - 1) * 64 + d];
        sT[(row * 32 + i) * TLD + d] = v;
    }
    __syncthreads();

    const float* tb = sT + warp * 32 * TLD;
    wmma::fragment<wmma::accumulator, 16, 16, 8, float> z[2][2];
    #pragma unroll
    for (int i = 0; i < 2; i++)
        #pragma unroll
        for (int j = 0; j < 2; j++) wmma::fill_fragment(z[i][j], 0.f);

    #pragma unroll
    for (int ks = 0; ks < 8; ks++) {
        wmma::fragment<wmma::matrix_a, 16, 16, 8, wmma::precision::tf32, wmma::row_major> af[2];
        wmma::fragment<wmma::matrix_b, 16, 16, 8, wmma::precision::tf32, wmma::col_major> bf[2];
        #pragma unroll
        for (int ti = 0; ti < 2; ti++) {
            wmma::load_matrix_sync(af[ti], tb + (ti * 16) * TLD + ks * 8, TLD);
            #pragma unroll
            for (int t = 0; t < af[ti].num_elements; t++)
                af[ti].x[t] = wmma::__float_to_tf32(af[ti].x[t]);
            wmma::load_matrix_sync(bf[ti], tb + (ti * 16) * TLD + ks * 8, TLD);
            #pragma unroll
            for (int t = 0; t < bf[ti].num_elements; t++)
                bf[ti].x[t] = wmma::__float_to_tf32(bf[ti].x[t]);
        }
        #pragma unroll
        for (int ti = 0; ti < 2; ti++)
            #pragma unroll
            for (int tj = 0; tj < 2; tj++)
                wmma::mma_sync(z[ti][tj], af[ti], bf[tj], z[ti][tj]);
    }

    float* Rb = R + (size_t)(b0 + warp) * 416;
    #pragma unroll
    for (int d = lane; d < 64; d += 32) Rb[d] = tb[d];
    if (lane == 0) Rb[415] = 0.f;

    // frags (0,0), (1,0), (1,1) contain lower-tri entries
    #pragma unroll
    for (int ti = 0; ti < 2; ti++) {
        #pragma unroll
        for (int tj = 0; tj <= ti; tj++) {
            wmma::store_matrix_sync(&sZ[warp][0][0], z[ti][tj], KPAD, wmma::mem_row_major);
            __syncwarp();
            int r = lane >> 1, c0 = (lane & 1) * 8;
            int gi = ti * 16 + r;
            #pragma unroll
            for (int c = 0; c < 8; c++) {
                int gj = tj * 16 + c0 + c;
                if (gi > gj && gi >= 1 && gi <= 26)
                    Rb[64 + gi * (gi - 1) / 2 + gj] = sZ[warp][r][c0 + c];
            }
            __syncwarp();
        }
    }
}

// ---------------------------------------------------------------------------
// Pad top_W1 [512,415] -> Wp [512,416] (col 415 = 0)
// ---------------------------------------------------------------------------
__global__ void __launch_bounds__(256) padw_kernel(
    const float* __restrict__ w, float* __restrict__ wp)
{
    int i = blockIdx.x * 256 + threadIdx.x;
    if (i >= 512 * 416) return;
    int n = i / 416, c = i - n * 416;
    wp[i] = (c < 415) ? w[n * 415 + c] : 0.f;
}

// ---------------------------------------------------------------------------
// Top MLP layer 3: [B,256] x [1,256]^T + b -> sigmoid -> out [B,1]
// ---------------------------------------------------------------------------
__global__ void __launch_bounds__(256) top3_kernel(
    const float* __restrict__ z2, const float* __restrict__ W,
    const float* __restrict__ bias, float* __restrict__ out)
{
    int warp = (blockIdx.x * 256 + threadIdx.x) >> 5;
    int lane = threadIdx.x & 31;
    if (warp >= B_) return;
    const float* zr = z2 + (size_t)warp * 256;
    float acc = 0.f;
    #pragma unroll
    for (int u = 0; u < 8; u++) acc = fmaf(zr[lane + 32 * u], W[lane + 32 * u], acc);
    #pragma unroll
    for (int o = 16; o > 0; o >>= 1) acc += __shfl_xor_sync(0xffffffffu, acc, o);
    if (lane == 0) out[warp] = 1.f / (1.f + expf(-(acc + bias[0])));
}

// ---------------------------------------------------------------------------
extern "C" void kernel_launch(void* const* d_in, const int* in_sizes, int n_in,
                              void* d_out, int out_size)
{
    const float* x    = (const float*)d_in[0];
    const int*   lS_i = (const int*)d_in[1];
    const float* emb  = (const float*)d_in[3];
    const float* bW1  = (const float*)d_in[4];
    const float* bb1  = (const float*)d_in[5];
    const float* bW2  = (const float*)d_in[6];
    const float* bb2  = (const float*)d_in[7];
    const float* bW3  = (const float*)d_in[8];
    const float* bb3  = (const float*)d_in[9];
    const float* tW1  = (const float*)d_in[10];
    const float* tb1  = (const float*)d_in[11];
    const float* tW2  = (const float*)d_in[12];
    const float* tb2  = (const float*)d_in[13];
    const float* tW3  = (const float*)d_in[14];
    const float* tb3  = (const float*)d_in[15];
    float* out = (float*)d_out;

    float* base;
    cudaGetSymbolAddress((void**)&base, g_scratch);
    float* h1  = base;                        // [B,512]
    float* h2  = h1  + (size_t)B_ * 512;      // [B,256]
    float* h3  = h2  + (size_t)B_ * 256;      // [B,64]
    float* T26 = h3  + (size_t)B_ * 64;       // [B,26,64]
    float* R   = T26 + (size_t)B_ * 1664;     // [B,416]
    float* z1  = R   + (size_t)B_ * 416;      // [B,512]
    float* z2  = z1  + (size_t)B_ * 512;      // [B,256]
    float* Wp  = z2  + (size_t)B_ * 256;      // [512,416]

    static_assert(true, "");
    cudaFuncSetAttribute(interact_kernel,
                         cudaFuncAttributeMaxDynamicSharedMemorySize,
                         8 * 32 * TLD * (int)sizeof(float));

    padw_kernel<<<(512 * 416 + 255) / 256, 256>>>(tW1, Wp);

    // embedding pooling (independent of MLP chain)
    emb_pool_kernel<<<(NT_ * B_ * 16) / 256, 256>>>(lS_i, emb, T26);

    // bottom MLP
    botl1_kernel<<<B_ / 16, 256>>>(x, bW1, bb1, h1);
    gemm_tf32<128, 128, 4, 2><<<dim3(B_ / 128, 2), 256>>>(h1, 512, bW2, 512, bb2,
                                                          h2, 256, 512);
    gemm_tf32<64, 64, 4, 2><<<dim3(B_ / 64, 1), 256>>>(h2, 256, bW3, 256, bb3,
                                                       h3, 64, 256);

    // interaction (h3 + pooled embeddings -> R)
    interact_kernel<<<B_ / 8, 256, 8 * 32 * TLD * sizeof(float)>>>(h3, T26, R);

    // top MLP
    gemm_tf32<128, 128, 4, 2><<<dim3(B_ / 128, 4), 256>>>(R, 416, Wp, 416, tb1,
                                                          z1, 512, 416);
    gemm_tf32<128, 128, 4, 2><<<dim3(B_ / 128, 2), 256>>>(z1, 512, tW2, 512, tb2,
                                                          z2, 256, 512);
    top3_kernel<<<(B_ * 32) / 256, 256>>>(z2, tW3, tb3, out);
}

// round 3
// speedup vs baseline: 1.0629x; 1.0362x over previous
#include <cuda_runtime.h>
#include <mma.h>
#include <math.h>

using namespace nvcuda;

#define B_   8192
#define L_   10
#define NT_  26
#define V_   200000
#define HB_  4096              // half batch

// per-row scratch: h1(512) h2(256) h3(64) T26(1664) R(416) z1(512) z2(256) = 3680
// plus padded top_W1 [512][416]
__device__ __align__(256) float g_scratch[(size_t)B_ * 3680 + 512 * 416];

// groups per half: 26*4096/16
#define EGROUPS 6656
// embA chunk split (hosted by botl1, botL2, botL3)
#define EA1 1480
#define EA2 2220
#define EA3 (EGROUPS - EA1 - EA2)
// embB chunk split (hosted by interactA, topL1A, topL2A, top3A)
#define EB1 1480
#define EB2 2220
#define EB3 1480
#define EB4 (EGROUPS - EB1 - EB2 - EB3)

// ---------------------------------------------------------------------------
// cp.async helpers
// ---------------------------------------------------------------------------
__device__ __forceinline__ void cp16(void* smem, const void* gmem) {
    unsigned s = (unsigned)__cvta_generic_to_shared(smem);
    asm volatile("cp.async.ca.shared.global [%0], [%1], 16;\n" :: "r"(s), "l"(gmem));
}
__device__ __forceinline__ void cp_commit() { asm volatile("cp.async.commit_group;\n"); }
template<int N> __device__ __forceinline__ void cp_wait() {
    asm volatile("cp.async.wait_group %0;\n" :: "n"(N));
}

// ---------------------------------------------------------------------------
// Embedding-bag pooling for one hybrid block: 16 bags, 16 threads per bag.
// half selects batch rows [half*4096, ...). g = group id within half.
// ---------------------------------------------------------------------------
__device__ __forceinline__ void emb_group_block(
    const int* __restrict__ lS_i, const float* __restrict__ tables,
    float* __restrict__ T26, int half, int g, int tid)
{
    int sub = tid >> 4;
    int lane = tid & 15;
    int w = g * 16 + sub;                 // within-half bag id, < 26*4096
    int t = w >> 12;                      // table
    int b = (half << 12) | (w & 4095);    // batch row
    const int* idx = lS_i + (size_t)t * (B_ * L_) + (size_t)b * L_;
    const float* tab = tables + (size_t)t * (V_ * 64);
    float4 acc = make_float4(0.f, 0.f, 0.f, 0.f);
    #pragma unroll
    for (int l = 0; l < L_; l++) {
        int r = idx[l];
        float4 v = ((const float4*)(tab + (size_t)r * 64))[lane];
        acc.x += v.x; acc.y += v.y; acc.z += v.z; acc.w += v.w;
    }
    ((float4*)(T26 + (size_t)b * 1664 + (size_t)t * 64))[lane] = acc;
}

// ---------------------------------------------------------------------------
// Bottom MLP layer 1 (hybrid): [B,13] x [512,13]^T + b, ReLU -> h1 [B,512]
// main blocks: B/16 = 512
// ---------------------------------------------------------------------------
__global__ void __launch_bounds__(256) botl1_kernel(
    const float* __restrict__ x, const float* __restrict__ W,
    const float* __restrict__ bias, float* __restrict__ h1,
    int mainBlocks,
    const int* __restrict__ lS_i, const float* __restrict__ tables,
    float* __restrict__ T26, int half, int gStart)
{
    if ((int)blockIdx.x >= mainBlocks) {
        emb_group_block(lS_i, tables, T26, half,
                        gStart + (int)blockIdx.x - mainBlocks, threadIdx.x);
        return;
    }
    __shared__ float Ws[512 * 13];
    __shared__ float bs[512];
    __shared__ float xs[16 * 13];
    int r0 = blockIdx.x * 16;
    for (int i = threadIdx.x; i < 512 * 13; i += 256) Ws[i] = W[i];
    for (int i = threadIdx.x; i < 512; i += 256) bs[i] = bias[i];
    for (int i = threadIdx.x; i < 16 * 13; i += 256) xs[i] = x[r0 * 13 + i];
    __syncthreads();
    #pragma unroll
    for (int cp = 0; cp < 2; cp++) {
        int c = threadIdx.x + cp * 256;
        float wreg[13];
        #pragma unroll
        for (int k = 0; k < 13; k++) wreg[k] = Ws[c * 13 + k];
        float bb = bs[c];
        #pragma unroll
        for (int r = 0; r < 16; r++) {
            float acc = bb;
            #pragma unroll
            for (int k = 0; k < 13; k++) acc = fmaf(wreg[k], xs[r * 13 + k], acc);
            h1[(size_t)(r0 + r) * 512 + c] = fmaxf(acc, 0.f);
        }
    }
}

// ---------------------------------------------------------------------------
// tf32 wmma GEMM (hybrid): out = relu(X[M,lda] @ W[N,ldw]^T + bias)
// BM=128 BN=64, 8 warps (4x2), per-warp 32x32 (2x2 frags). BK=16, dbl-buffer.
// Raw fp32 bits fed to tf32 mma (hardware truncates low 13 bits).
// ---------------------------------------------------------------------------
#define BK   16
#define KPAD 20

__global__ void __launch_bounds__(256, 2) gemm_tf32(
    const float* __restrict__ X, int lda,
    const float* __restrict__ W, int ldw,
    const float* __restrict__ bias,
    float* __restrict__ out, int ldc, int K,
    int mainX, int mainBlocks,
    const int* __restrict__ lS_i, const float* __restrict__ tables,
    float* __restrict__ T26, int half, int gStart)
{
    if ((int)blockIdx.x >= mainBlocks) {
        emb_group_block(lS_i, tables, T26, half,
                        gStart + (int)blockIdx.x - mainBlocks, threadIdx.x);
        return;
    }
    __shared__ float As[2][128][KPAD];
    __shared__ float Bs[2][64][KPAD];
    int tid = threadIdx.x;
    int warp = tid >> 5;
    int lane = tid & 31;
    int wm = warp >> 1, wn = warp & 1;          // 4 x 2 warp grid
    int bx = (int)blockIdx.x % mainX, by = (int)blockIdx.x / mainX;
    int m0 = bx * 128, n0 = by * 64;

    wmma::fragment<wmma::accumulator, 16, 16, 8, float> acc[2][2];
    #pragma unroll
    for (int i = 0; i < 2; i++)
        #pragma unroll
        for (int j = 0; j < 2; j++) wmma::fill_fragment(acc[i][j], 0.f);

    auto load_tile = [&](int buf, int k0) {
        #pragma unroll
        for (int i = tid; i < 128 * 4; i += 256) {
            int r = i >> 2, s = (i & 3) * 4;
            cp16(&As[buf][r][s], X + (size_t)(m0 + r) * lda + k0 + s);
        }
        #pragma unroll
        for (int i = tid; i < 64 * 4; i += 256) {
            int r = i >> 2, s = (i & 3) * 4;
            cp16(&Bs[buf][r][s], W + (size_t)(n0 + r) * ldw + k0 + s);
        }
        cp_commit();
    };

    int nIter = K / BK;
    load_tile(0, 0);
    int buf = 0;
    for (int it = 0; it < nIter; it++) {
        if (it + 1 < nIter) { load_tile(buf ^ 1, (it + 1) * BK); cp_wait<1>(); }
        else cp_wait<0>();
        __syncthreads();
        #pragma unroll
        for (int ks = 0; ks < 2; ks++) {
            wmma::fragment<wmma::matrix_a, 16, 16, 8, wmma::precision::tf32, wmma::row_major> af[2];
            wmma::fragment<wmma::matrix_b, 16, 16, 8, wmma::precision::tf32, wmma::col_major> bf[2];
            #pragma unroll
            for (int mi = 0; mi < 2; mi++)
                wmma::load_matrix_sync(af[mi], &As[buf][wm * 32 + mi * 16][ks * 8], KPAD);
            #pragma unroll
            for (int nj = 0; nj < 2; nj++)
                wmma::load_matrix_sync(bf[nj], &Bs[buf][wn * 32 + nj * 16][ks * 8], KPAD);
            #pragma unroll
            for (int mi = 0; mi < 2; mi++)
                #pragma unroll
                for (int nj = 0; nj < 2; nj++)
                    wmma::mma_sync(acc[mi][nj], af[mi], bf[nj], acc[mi][nj]);
        }
        __syncthreads();
        buf ^= 1;
    }

    // epilogue: per-warp 16x16 staging, +bias, relu
    float* es = &As[0][0][0] + warp * 16 * KPAD;
    #pragma unroll
    for (int mi = 0; mi < 2; mi++) {
        #pragma unroll
        for (int nj = 0; nj < 2; nj++) {
            wmma::store_matrix_sync(es, acc[mi][nj], KPAD, wmma::mem_row_major);
            __syncwarp();
            int r = lane >> 1, c0 = (lane & 1) * 8;
            int gm = m0 + wm * 32 + mi * 16 + r;
            int gn = n0 + wn * 32 + nj * 16 + c0;
            #pragma unroll
            for (int c = 0; c < 8; c++) {
                float v = es[r * KPAD + c0 + c] + bias[gn + c];
                out[(size_t)gm * ldc + gn + c] = fmaxf(v, 0.f);
            }
            __syncwarp();
        }
    }
}

// ---------------------------------------------------------------------------
// Dot interaction (hybrid, per half): Z = T T^T, R = [h3, tril(Z)]
// main blocks: 4096/8 = 512 (8 warps = 8 batch rows per block)
// ---------------------------------------------------------------------------
#define TLD 68

__global__ void __launch_bounds__(256) interact_kernel(
    const float* __restrict__ h3, const float* __restrict__ T26,
    float* __restrict__ R, int half,
    int mainBlocks,
    const int* __restrict__ lS_i, const float* __restrict__ tables,
    float* __restrict__ T26w, int ehalf, int gStart)
{
    if ((int)blockIdx.x >= mainBlocks) {
        emb_group_block(lS_i, tables, T26w, ehalf,
                        gStart + (int)blockIdx.x - mainBlocks, threadIdx.x);
        return;
    }
    extern __shared__ float sT[];          // 8 * 32 * TLD floats
    __shared__ float sZ[8][16][KPAD];
    int tid = threadIdx.x, warp = tid >> 5, lane = tid & 31;
    int b0 = half * HB_ + blockIdx.x * 8;

    for (int idx = tid; idx < 8 * 32 * 64; idx += 256) {
        int row = idx >> 11;
        int e = idx & 2047;
        int i = e >> 6, d = e & 63;
        float v = 0.f;
        if (i == 0)       v = h3[(size_t)(b0 + row) * 64 + d];
        else if (i < 27)  v = T26[(size_t)(b0 + row) * 1664 + (i - 1) * 64 + d];
        sT[(row * 32 + i) * TLD + d] = v;
    }
    __syncthreads();

    const float* tb = sT + warp * 32 * TLD;
    wmma::fragment<wmma::accumulator, 16, 16, 8, float> z[2][2];
    #pragma unroll
    for (int i = 0; i < 2; i++)
        #pragma unroll
        for (int j = 0; j < 2; j++) wmma::fill_fragment(z[i][j], 0.f);

    #pragma unroll
    for (int ks = 0; ks < 8; ks++) {
        wmma::fragment<wmma::matrix_a, 16, 16, 8, wmma::precision::tf32, wmma::row_major> af[2];
        wmma::fragment<wmma::matrix_b, 16, 16, 8, wmma::precision::tf32, wmma::col_major> bf[2];
        #pragma unroll
        for (int ti = 0; ti < 2; ti++) {
            wmma::load_matrix_sync(af[ti], tb + (ti * 16) * TLD + ks * 8, TLD);
            wmma::load_matrix_sync(bf[ti], tb + (ti * 16) * TLD + ks * 8, TLD);
        }
        #pragma unroll
        for (int ti = 0; ti < 2; ti++)
            #pragma unroll
            for (int tj = 0; tj < 2; tj++)
                wmma::mma_sync(z[ti][tj], af[ti], bf[tj], z[ti][tj]);
    }

    float* Rb = R + (size_t)(b0 + warp) * 416;
    #pragma unroll
    for (int d = lane; d < 64; d += 32) Rb[d] = tb[d];
    if (lane == 0) Rb[415] = 0.f;

    #pragma unroll
    for (int ti = 0; ti < 2; ti++) {
        #pragma unroll
        for (int tj = 0; tj <= ti; tj++) {
            wmma::store_matrix_sync(&sZ[warp][0][0], z[ti][tj], KPAD, wmma::mem_row_major);
            __syncwarp();
            int r = lane >> 1, c0 = (lane & 1) * 8;
            int gi = ti * 16 + r;
            #pragma unroll
            for (int c = 0; c < 8; c++) {
                int gj = tj * 16 + c0 + c;
                if (gi > gj && gi >= 1 && gi <= 26)
                    Rb[64 + gi * (gi - 1) / 2 + gj] = sZ[warp][r][c0 + c];
            }
            __syncwarp();
        }
    }
}

// ---------------------------------------------------------------------------
// Pad top_W1 [512,415] -> Wp [512,416] (col 415 = 0)
// ---------------------------------------------------------------------------
__global__ void __launch_bounds__(256) padw_kernel(
    const float* __restrict__ w, float* __restrict__ wp)
{
    int i = blockIdx.x * 256 + threadIdx.x;
    if (i >= 512 * 416) return;
    int n = i / 416, c = i - n * 416;
    wp[i] = (c < 415) ? w[n * 415 + c] : 0.f;
}

// ---------------------------------------------------------------------------
// Top MLP layer 3 (hybrid, per half): sigmoid(z2 . W + b) -> out
// main blocks: 4096/8 = 512 (one warp per row)
// ---------------------------------------------------------------------------
__global__ void __launch_bounds__(256) top3_kernel(
    const float* __restrict__ z2, const float* __restrict__ W,
    const float* __restrict__ bias, float* __restrict__ out, int half,
    int mainBlocks,
    const int* __restrict__ lS_i, const float* __restrict__ tables,
    float* __restrict__ T26w, int ehalf, int gStart)
{
    if ((int)blockIdx.x >= mainBlocks) {
        emb_group_block(lS_i, tables, T26w, ehalf,
                        gStart + (int)blockIdx.x - mainBlocks, threadIdx.x);
        return;
    }
    int gw = blockIdx.x * 8 + (threadIdx.x >> 5);
    int lane = threadIdx.x & 31;
    int row = half * HB_ + gw;
    const float* zr = z2 + (size_t)row * 256;
    float acc = 0.f;
    #pragma unroll
    for (int u = 0; u < 8; u++) acc = fmaf(zr[lane + 32 * u], W[lane + 32 * u], acc);
    #pragma unroll
    for (int o = 16; o > 0; o >>= 1) acc += __shfl_xor_sync(0xffffffffu, acc, o);
    if (lane == 0) out[row] = 1.f / (1.f + expf(-(acc + bias[0])));
}

// ---------------------------------------------------------------------------
extern "C" void kernel_launch(void* const* d_in, const int* in_sizes, int n_in,
                              void* d_out, int out_size)
{
    const float* x    = (const float*)d_in[0];
    const int*   lS_i = (const int*)d_in[1];
    const float* emb  = (const float*)d_in[3];
    const float* bW1  = (const float*)d_in[4];
    const float* bb1  = (const float*)d_in[5];
    const float* bW2  = (const float*)d_in[6];
    const float* bb2  = (const float*)d_in[7];
    const float* bW3  = (const float*)d_in[8];
    const float* bb3  = (const float*)d_in[9];
    const float* tW1  = (const float*)d_in[10];
    const float* tb1  = (const float*)d_in[11];
    const float* tW2  = (const float*)d_in[12];
    const float* tb2  = (const float*)d_in[13];
    const float* tW3  = (const float*)d_in[14];
    const float* tb3  = (const float*)d_in[15];
    float* out = (float*)d_out;

    float* base;
    cudaGetSymbolAddress((void**)&base, g_scratch);
    float* h1  = base;                        // [B,512]
    float* h2  = h1  + (size_t)B_ * 512;      // [B,256]
    float* h3  = h2  + (size_t)B_ * 256;      // [B,64]
    float* T26 = h3  + (size_t)B_ * 64;       // [B,26,64]
    float* R   = T26 + (size_t)B_ * 1664;     // [B,416]
    float* z1  = R   + (size_t)B_ * 416;      // [B,512]
    float* z2  = z1  + (size_t)B_ * 512;      // [B,256]
    float* Wp  = z2  + (size_t)B_ * 256;      // [512,416]

    cudaFuncSetAttribute(interact_kernel,
                         cudaFuncAttributeMaxDynamicSharedMemorySize,
                         8 * 32 * TLD * (int)sizeof(float));
    int ismem = 8 * 32 * TLD * sizeof(float);

    padw_kernel<<<(512 * 416 + 255) / 256, 256>>>(tW1, Wp);

    // ---- phase 1: bottom MLP (full batch), hosting embA chunks ----
    botl1_kernel<<<512 + EA1, 256>>>(x, bW1, bb1, h1,
                                     512, lS_i, emb, T26, 0, 0);
    gemm_tf32<<<256 + EA2, 256>>>(h1, 512, bW2, 512, bb2, h2, 256, 512,
                                  64, 256, lS_i, emb, T26, 0, EA1);
    gemm_tf32<<<64 + EA3, 256>>>(h2, 256, bW3, 256, bb3, h3, 64, 256,
                                 64, 64, lS_i, emb, T26, 0, EA1 + EA2);

    // ---- phase 2: half 0 interact+top, hosting embB chunks ----
    interact_kernel<<<512 + EB1, 256, ismem>>>(h3, T26, R, 0,
                                               512, lS_i, emb, T26, 1, 0);
    gemm_tf32<<<256 + EB2, 256>>>(R, 416, Wp, 416, tb1,
                                  z1 + (size_t)0, 512, 416,
                                  32, 256, lS_i, emb, T26, 1, EB1);
    gemm_tf32<<<128 + EB3, 256>>>(z1, 512, tW2, 512, tb2, z2, 256, 512,
                                  32, 128, lS_i, emb, T26, 1, EB1 + EB2);
    top3_kernel<<<512 + EB4, 256>>>(z2, tW3, tb3, out, 0,
                                    512, lS_i, emb, T26, 1, EB1 + EB2 + EB3);

    // ---- phase 3: half 1 interact+top (embB complete) ----
    interact_kernel<<<512, 256, ismem>>>(h3, T26, R, 1,
                                         512, lS_i, emb, T26, 1, 0);
    gemm_tf32<<<256, 256>>>(R + (size_t)HB_ * 416, 416, Wp, 416, tb1,
                            z1 + (size_t)HB_ * 512, 512, 416,
                            32, 256, lS_i, emb, T26, 1, 0);
    gemm_tf32<<<128, 256>>>(z1 + (size_t)HB_ * 512, 512, tW2, 512, tb2,
                            z2 + (size_t)HB_ * 256, 256, 512,
                            32, 128, lS_i, emb, T26, 1, 0);
    top3_kernel<<<512, 256>>>(z2, tW3, tb3, out, 1,
                              512, lS_i, emb, T26, 1, 0);
}